// round 14
// baseline (speedup 1.0000x reference)
#include <cuda_runtime.h>

#define TPB 256
typedef unsigned long long u64;

// smem floats:
// srkT 12200 | sIfbn 3600 | sPart 20*56=1120 | srbk 200 | sr 100 | srn 100 |
// sbias 100 | sWro 20 | srbd 20 | srbd2 40 | snrd2 40  => 17540 floats = 70160 B
#define SMEM_FLOATS 17540

__device__ __forceinline__ u64 pk(float lo, float hi) {
    u64 r; asm("mov.b64 %0,{%1,%2};" : "=l"(r) : "f"(lo), "f"(hi)); return r;
}
__device__ __forceinline__ void upk(u64 v, float& lo, float& hi) {
    asm("mov.b64 {%0,%1},%2;" : "=f"(lo), "=f"(hi) : "l"(v));
}
__device__ __forceinline__ u64 fma2(u64 a, u64 b, u64 c) {
    u64 d; asm("fma.rn.f32x2 %0,%1,%2,%3;" : "=l"(d) : "l"(a), "l"(b), "l"(c)); return d;
}
__device__ __forceinline__ u64 mul2(u64 a, u64 b) {
    u64 d; asm("mul.rn.f32x2 %0,%1,%2;" : "=l"(d) : "l"(a), "l"(b)); return d;
}
__device__ __forceinline__ u64 add2(u64 a, u64 b) {
    u64 d; asm("add.rn.f32x2 %0,%1,%2;" : "=l"(d) : "l"(a), "l"(b)); return d;
}

__global__ void __launch_bounds__(256, 2)
rnn_kernel(const float* __restrict__ r_kc, const float* __restrict__ r_ext,
           const float* __restrict__ W0_W, const float* __restrict__ W0_w,
           const float* __restrict__ W_recur, const float* __restrict__ W_ext,
           const float* __restrict__ bias, const float* __restrict__ W_readout,
           float* __restrict__ out, int nb)
{
    const int b   = blockIdx.x;
    const int tid = threadIdx.x;
    const int wid = tid >> 5, lane = tid & 31;

    extern __shared__ float smem[];
    float* srkT   = smem;            // 12200 : rk [t*200+k], 61 steps
    float* sIfbn  = smem + 12200;    // 3600  : precomputed I_fbn [t*60+f]
    float* sPart  = smem + 15800;    // 1120  : partials, row stride 56, gap 25..27
    float* srbk   = smem + 16920;    // 200
    float* sr     = smem + 17120;    // 100
    float* srn    = smem + 17220;    // 100
    float* sbias  = smem + 17320;    // 100
    float* sWro   = smem + 17420;    // 20
    float* srbd   = smem + 17440;    // 20
    float* srbd2f = smem + 17460;    // 40 (u64[20])
    float* snrd2f = smem + 17500;    // 40 (u64[20])

    const float dt  = 0.5f;   // time = arange*0.5 -> exact
    const float dtw = 0.1f;   // dt / TAU_W
    const u64 DT2   = pk(dt, dt);
    const u64 DTW2  = pk(dtw, dtw);
    const u64 NEG12 = pk(-1.0f, -1.0f);

    const size_t nb4000 = (size_t)nb * 4000;
    const size_t OFF_W  = (size_t)61 * nb * 100;
    const size_t OFF_WT = OFF_W + (size_t)61 * nb4000;
    const size_t OFF_RO = OFF_WT + (size_t)61 * nb4000;

    // ---- init: bulk-load rk (transposed), precompute I_fbn for all steps ----
    const float* rkb = r_kc  + (size_t)b * (200 * 61);
    const float* reb = r_ext + (size_t)b * (2 * 61);
    for (int idx = tid; idx < 12200; idx += TPB) {
        int k = idx / 61, t = idx - k * 61;
        srkT[t * 200 + k] = rkb[idx];
    }
    for (int idx = tid; idx < 3600; idx += TPB) {
        int t = idx / 60, f = idx - t * 60;
        sIfbn[idx] = W_ext[2 * f] * reb[t] + W_ext[2 * f + 1] * reb[61 + t];
    }
    if (tid < 100) sbias[tid] = bias[tid];
    if (tid < 20)  { sWro[tid] = W_readout[tid]; srbd[tid] = 0.1f; }
    if (tid < 100) {
        float v = (tid < 20) ? 0.0f : 0.1f;
        sr[tid] = v;
        out[(size_t)b * 100 + tid] = v;                 // r_series[0]
    }
    if (tid == 0) out[OFF_RO + b] = 0.0f;               // readout[0]

    // ---- Wr in packed registers: thread t<200 -> row s=t>>1, half h=t&1 ----
    const int s = tid >> 1, h = tid & 1;
    u64 wrr2[25];
    if (tid < 200) {
        const float2* src = (const float2*)(W_recur + s * 100 + h * 50);
#pragma unroll
        for (int i = 0; i < 25; i++) {
            float2 v = src[i];
            if (s < 20) {                                // MBON<-DAN zeroed
                int jcol = h * 50 + 2 * i;
                if (jcol >= 80) v.x = 0.0f;
                if (jcol + 1 >= 80) v.y = 0.0f;
            }
            wrr2[i] = pk(v.x, v.y);
        }
    } else {
#pragma unroll
        for (int i = 0; i < 25; i++) wrr2[i] = 0ull;
    }

    // ---- per-thread loop-invariant chunk geometry ----
    int m_[4], kq_[4], sp_[4];
    bool val_[4];
#pragma unroll
    for (int j = 0; j < 4; j++) {
        int c = tid + TPB * j; if (c > 999) c = 999;
        val_[j] = (tid + TPB * j) < 1000;
        int m = c / 50, kq = c - m * 50;
        m_[j] = m; kq_[j] = kq;
        sp_[j] = m * 56 + kq + ((kq >= 25) ? 3 : 0);
    }

    // ---- W (float4) + wt (packed u64) state + series[0] stores ----
    float4 rw[4];
    u64 rwt2[8];
    {
        const float4* gW0 = (const float4*)(W0_W + (size_t)b * 4000);
        const ulonglong2* gw0 = (const ulonglong2*)(W0_w + (size_t)b * 4000);
        float4* oW0  = (float4*)(out + OFF_W  + (size_t)b * 4000) + tid;
        float4* owt0 = (float4*)(out + OFF_WT + (size_t)b * 4000) + tid;
#pragma unroll
        for (int j = 0; j < 4; j++) {
            if (val_[j]) {
                int c = tid + TPB * j;
                float4 w = gW0[c];
                ulonglong2 wt = gw0[c];
                rw[j] = w; rwt2[2 * j] = wt.x; rwt2[2 * j + 1] = wt.y;
                __stcs(oW0 + 256 * j, w);
                float a, b2, c2, d2; upk(wt.x, a, b2); upk(wt.y, c2, d2);
                __stcs(owt0 + 256 * j, make_float4(a, b2, c2, d2));
            }
        }
    }
    __syncthreads();

    // ---- rbk0 + seed sPart = W0 . rk(0) ----
    if (tid < 200) srbk[tid] = srkT[tid];
    {
        const float4* rk4 = (const float4*)srkT;        // t = 0
#pragma unroll
        for (int j = 0; j < 4; j++) {
            if (val_[j]) {
                float4 x = rk4[kq_[j]];
                float4 w = rw[j];
                sPart[sp_[j]] = w.x * x.x + w.y * x.y + w.z * x.z + w.w * x.w;
            }
        }
    }
    __syncthreads();

    const float* srkC = srkT;                           // rk(t) running ptr
    float* oWf  = out + OFF_W  + (size_t)b * 4000;      // running series ptrs
    float* owtf = out + OFF_WT + (size_t)b * 4000;

    // ---- 60 steps, 2 barriers each ----
    for (int t = 0; t < 60; t++) {
        oWf += nb4000; owtf += nb4000;

        // ---- Phase B: r dynamics (packed register matvec) / rbk update ----
        if (tid < 200) {
            const u64* rr2 = (const u64*)(sr + h * 50);
            u64 a0 = 0ull, a1 = 0ull;
#pragma unroll
            for (int i = 0; i < 24; i += 2) {
                a0 = fma2(wrr2[i],     rr2[i],     a0);
                a1 = fma2(wrr2[i + 1], rr2[i + 1], a1);
            }
            a0 = fma2(wrr2[24], rr2[24], a0);
            float tail = 0.0f;
            if (s < 20) {                                // I_kc partial sums
                const u64* p2 = (const u64*)(sPart + s * 56 + h * 28);
#pragma unroll
                for (int i = 0; i < 12; i += 2) {
                    a0 = add2(a0, p2[i]);
                    a1 = add2(a1, p2[i + 1]);
                }
                tail = (sPart + s * 56 + h * 28)[24];
            }
            float f0, f1, f2, f3;
            upk(a0, f0, f1); upk(a1, f2, f3);
            float acc = (f0 + f1) + (f2 + f3) + tail;
            if (h == 0) {
                float I = (s >= 20 && s < 80) ? sIfbn[t * 60 + (s - 20)] : 0.0f;
                acc += sbias[s] + I;
            }
            unsigned msk = (tid < 192) ? 0xFFFFFFFFu : 0x000000FFu;
            acc += __shfl_xor_sync(msk, acc, 1);
            if (h == 0) {
                float act  = fmaxf(acc, 0.0f);
                float rold = sr[s];
                float rn   = rold + (act - rold) * dt;   // TAU_R = 1
                srn[s] = rn;
                if (s >= 80) {                           // barrier-critical smem
                    int d = s - 80;                      // publishes FIRST
                    float nv = srbd[d] + (rn - srbd[d]) * dtw;
                    srbd[d] = nv;
                    *(u64*)(srbd2f + 2 * d) = pk(nv, nv);
                    *(u64*)(snrd2f + 2 * d) = pk(-rn, -rn);
                }
                __stcs(out + ((size_t)(t + 1) * nb + b) * 100 + s, rn);
            }
        } else {
            int u = tid - 200;                           // rbk: 100 u64s, packed
            u64* rb2 = (u64*)srbk;
            const u64* rk2 = (const u64*)srkC;
            {
                u64 rb = rb2[u];
                u64 d = fma2(rb, NEG12, rk2[u]);
                rb2[u] = fma2(d, DTW2, rb);
            }
            if (u < 44) {
                int k = u + 56;
                u64 rb = rb2[k];
                u64 d = fma2(rb, NEG12, rk2[k]);
                rb2[k] = fma2(d, DTW2, rb);
            }
        }
        __syncthreads();

        // ---- Phase D: plasticity + streamed stores + next sPart ----
        if (wid == 0) {                                  // readout[t+1]
            float p = (lane < 20) ? sWro[lane] * srn[lane] : 0.0f;
            p += __shfl_xor_sync(0xffffffffu, p, 16);
            p += __shfl_xor_sync(0xffffffffu, p, 8);
            p += __shfl_xor_sync(0xffffffffu, p, 4);
            p += __shfl_xor_sync(0xffffffffu, p, 2);
            p += __shfl_xor_sync(0xffffffffu, p, 1);
            if (lane == 0) out[OFF_RO + (size_t)(t + 1) * nb + b] = p;
        }
        {
            float4* oW4  = (float4*)oWf  + tid;
            float4* owt4 = (float4*)owtf + tid;
            const ulonglong2* rkv  = (const ulonglong2*)srkC;
            const ulonglong2* rnv  = (const ulonglong2*)(srkC + 200);
            const ulonglong2* rbkv = (const ulonglong2*)srbk;
#pragma unroll
            for (int j = 0; j < 4; j++) {
                if (val_[j]) {
                    int m  = m_[j];
                    int kq = kq_[j];
                    u64 rbd2 = *(const u64*)(srbd2f + 2 * m);
                    u64 nrd2 = *(const u64*)(snrd2f + 2 * m);
                    ulonglong2 rk = rkv[kq];
                    ulonglong2 rb = rbkv[kq];
                    u64 t0 = mul2(rbd2, rk.x);
                    t0 = fma2(nrd2, rb.x, t0);
                    rwt2[2 * j] = fma2(t0, DT2, rwt2[2 * j]);
                    u64 t1 = mul2(rbd2, rk.y);
                    t1 = fma2(nrd2, rb.y, t1);
                    rwt2[2 * j + 1] = fma2(t1, DT2, rwt2[2 * j + 1]);
                    float wtx, wty, wtz, wtw;
                    upk(rwt2[2 * j], wtx, wty);
                    upk(rwt2[2 * j + 1], wtz, wtw);
                    float4 w = rw[j];
                    w.x = fminf(fmaxf(fmaf(wtx - w.x, dtw, w.x), 0.0f), 0.05f);
                    w.y = fminf(fmaxf(fmaf(wty - w.y, dtw, w.y), 0.0f), 0.05f);
                    w.z = fminf(fmaxf(fmaf(wtz - w.z, dtw, w.z), 0.0f), 0.05f);
                    w.w = fminf(fmaxf(fmaf(wtw - w.w, dtw, w.w), 0.0f), 0.05f);
                    rw[j] = w;
                    // partial I_kc(t+1) with freshly-updated W
                    ulonglong2 xn = rnv[kq];
                    u64 a = mul2(pk(w.x, w.y), xn.x);
                    a = fma2(pk(w.z, w.w), xn.y, a);
                    float alo, ahi; upk(a, alo, ahi);
                    sPart[sp_[j]] = alo + ahi;
                    __stcs(oW4  + 256 * j, w);           // W_series[t+1]
                    __stcs(owt4 + 256 * j, make_float4(wtx, wty, wtz, wtw));
                }
            }
        }
        if (tid < 100) sr[tid] = srn[tid];               // carry r
        srkC += 200;
        __syncthreads();
    }
}

extern "C" void kernel_launch(void* const* d_in, const int* in_sizes, int n_in,
                              void* d_out, int out_size)
{
    const float* r_kc   = (const float*)d_in[0];
    const float* r_ext  = (const float*)d_in[1];
    // d_in[2] = time (dt = 0.5 exact), d_in[3] = n_batch scalar
    const float* W0_W   = (const float*)d_in[4];
    const float* W0_w   = (const float*)d_in[5];
    const float* W_rec  = (const float*)d_in[6];
    const float* W_ext  = (const float*)d_in[7];
    const float* bias   = (const float*)d_in[8];
    const float* W_ro   = (const float*)d_in[9];

    int nb = in_sizes[0] / (200 * 61);   // 256

    size_t smem = SMEM_FLOATS * sizeof(float);   // 70160 B
    cudaFuncSetAttribute(rnn_kernel, cudaFuncAttributeMaxDynamicSharedMemorySize,
                         (int)smem);

    rnn_kernel<<<nb, TPB, smem>>>(r_kc, r_ext, W0_W, W0_w, W_rec,
                                  W_ext, bias, W_ro, (float*)d_out, nb);
}

// round 15
// speedup vs baseline: 1.0534x; 1.0534x over previous
#include <cuda_runtime.h>

#define TPB 256
typedef unsigned long long u64;

// smem floats:
// srkT 12200 | sIfbn 3600 | sPart 20*56=1120 | srbk 200 | sr 100 | srn 100 |
// sbias 100 | sWro 20 | srbd 20 | sDN 80  => 17540 floats = 70160 B
#define SMEM_FLOATS 17540

__device__ __forceinline__ u64 pk(float lo, float hi) {
    u64 r; asm("mov.b64 %0,{%1,%2};" : "=l"(r) : "f"(lo), "f"(hi)); return r;
}
__device__ __forceinline__ void upk(u64 v, float& lo, float& hi) {
    asm("mov.b64 {%0,%1},%2;" : "=f"(lo), "=f"(hi) : "l"(v));
}
__device__ __forceinline__ u64 fma2(u64 a, u64 b, u64 c) {
    u64 d; asm("fma.rn.f32x2 %0,%1,%2,%3;" : "=l"(d) : "l"(a), "l"(b), "l"(c)); return d;
}
__device__ __forceinline__ u64 mul2(u64 a, u64 b) {
    u64 d; asm("mul.rn.f32x2 %0,%1,%2;" : "=l"(d) : "l"(a), "l"(b)); return d;
}
__device__ __forceinline__ u64 add2(u64 a, u64 b) {
    u64 d; asm("add.rn.f32x2 %0,%1,%2;" : "=l"(d) : "l"(a), "l"(b)); return d;
}

__global__ void __launch_bounds__(256, 2)
rnn_kernel(const float* __restrict__ r_kc, const float* __restrict__ r_ext,
           const float* __restrict__ W0_W, const float* __restrict__ W0_w,
           const float* __restrict__ W_recur, const float* __restrict__ W_ext,
           const float* __restrict__ bias, const float* __restrict__ W_readout,
           float* __restrict__ out, int nb)
{
    const int b   = blockIdx.x;
    const int tid = threadIdx.x;
    const int wid = tid >> 5, lane = tid & 31;

    extern __shared__ float smem[];
    float* srkT   = smem;            // 12200 : rk [t*200+k], 61 steps
    float* sIfbn  = smem + 12200;    // 3600  : precomputed I_fbn [t*60+f]
    float* sPart  = smem + 15800;    // 1120  : partials, row stride 56, gap 25..27
    float* srbk   = smem + 16920;    // 200
    float* sr     = smem + 17120;    // 100
    float* srn    = smem + 17220;    // 100
    float* sbias  = smem + 17320;    // 100
    float* sWro   = smem + 17420;    // 20
    float* srbd   = smem + 17440;    // 20
    float* sDN    = smem + 17460;    // 80 : float4[m] = {rbd,rbd,-rdan,-rdan}, 16B-aligned

    const float dt  = 0.5f;   // time = arange*0.5 -> exact
    const float dtw = 0.1f;   // dt / TAU_W
    const u64 DT2   = pk(dt, dt);
    const u64 DTW2  = pk(dtw, dtw);
    const u64 NEG12 = pk(-1.0f, -1.0f);

    const size_t nb4000 = (size_t)nb * 4000;
    const size_t OFF_W  = (size_t)61 * nb * 100;
    const size_t OFF_WT = OFF_W + (size_t)61 * nb4000;
    const size_t OFF_RO = OFF_WT + (size_t)61 * nb4000;

    // ---- init: bulk-load rk (transposed), precompute I_fbn for all steps ----
    const float* rkb = r_kc  + (size_t)b * (200 * 61);
    const float* reb = r_ext + (size_t)b * (2 * 61);
    for (int idx = tid; idx < 12200; idx += TPB) {
        int k = idx / 61, t = idx - k * 61;
        srkT[t * 200 + k] = rkb[idx];
    }
    for (int idx = tid; idx < 3600; idx += TPB) {
        int t = idx / 60, f = idx - t * 60;
        sIfbn[idx] = W_ext[2 * f] * reb[t] + W_ext[2 * f + 1] * reb[61 + t];
    }
    if (tid < 100) sbias[tid] = bias[tid];
    if (tid < 20)  { sWro[tid] = W_readout[tid]; srbd[tid] = 0.1f; }
    if (tid < 100) {
        float v = (tid < 20) ? 0.0f : 0.1f;
        sr[tid] = v;
        out[(size_t)b * 100 + tid] = v;                 // r_series[0]
    }
    if (tid == 0) out[OFF_RO + b] = 0.0f;               // readout[0]

    // ---- Wr in packed registers: thread t<200 -> row s=t>>1, half h=t&1 ----
    const int s = tid >> 1, h = tid & 1;
    u64 wrr2[25];
    if (tid < 200) {
        const float2* src = (const float2*)(W_recur + s * 100 + h * 50);
#pragma unroll
        for (int i = 0; i < 25; i++) {
            float2 v = src[i];
            if (s < 20) {                                // MBON<-DAN zeroed
                int jcol = h * 50 + 2 * i;
                if (jcol >= 80) v.x = 0.0f;
                if (jcol + 1 >= 80) v.y = 0.0f;
            }
            wrr2[i] = pk(v.x, v.y);
        }
    } else {
#pragma unroll
        for (int i = 0; i < 25; i++) wrr2[i] = 0ull;
    }

    // ---- per-thread loop-invariant chunk geometry ----
    int m_[4], kq_[4], sp_[4];
    bool val_[4];
#pragma unroll
    for (int j = 0; j < 4; j++) {
        int c = tid + TPB * j; if (c > 999) c = 999;
        val_[j] = (tid + TPB * j) < 1000;
        int m = c / 50, kq = c - m * 50;
        m_[j] = m; kq_[j] = kq;
        sp_[j] = m * 56 + kq + ((kq >= 25) ? 3 : 0);
    }

    // ---- W (float4) + wt (packed u64) state + series[0] stores ----
    float4 rw[4];
    u64 rwt2[8];
    {
        const float4* gW0 = (const float4*)(W0_W + (size_t)b * 4000);
        const ulonglong2* gw0 = (const ulonglong2*)(W0_w + (size_t)b * 4000);
        float4* oW0  = (float4*)(out + OFF_W  + (size_t)b * 4000) + tid;
        float4* owt0 = (float4*)(out + OFF_WT + (size_t)b * 4000) + tid;
#pragma unroll
        for (int j = 0; j < 4; j++) {
            if (val_[j]) {
                int c = tid + TPB * j;
                float4 w = gW0[c];
                ulonglong2 wt = gw0[c];
                rw[j] = w; rwt2[2 * j] = wt.x; rwt2[2 * j + 1] = wt.y;
                __stcs(oW0 + 256 * j, w);
                float a, b2, c2, d2; upk(wt.x, a, b2); upk(wt.y, c2, d2);
                __stcs(owt0 + 256 * j, make_float4(a, b2, c2, d2));
            }
        }
    }
    __syncthreads();

    // ---- rbk0 + seed sPart = W0 . rk(0) ----
    if (tid < 200) srbk[tid] = srkT[tid];
    {
        const float4* rk4 = (const float4*)srkT;        // t = 0
#pragma unroll
        for (int j = 0; j < 4; j++) {
            if (val_[j]) {
                float4 x = rk4[kq_[j]];
                float4 w = rw[j];
                sPart[sp_[j]] = w.x * x.x + w.y * x.y + w.z * x.z + w.w * x.w;
            }
        }
    }
    __syncthreads();

    const float* srkC = srkT;                           // rk(t) running ptr

    // ---- 60 steps, 2 barriers each ----
    for (int t = 0; t < 60; t++) {
        // ---- Phase B: r dynamics (packed register matvec) / rbk update ----
        if (tid < 200) {
            const u64* rr2 = (const u64*)(sr + h * 50);
            u64 a0 = 0ull, a1 = 0ull;
#pragma unroll
            for (int i = 0; i < 24; i += 2) {
                a0 = fma2(wrr2[i],     rr2[i],     a0);
                a1 = fma2(wrr2[i + 1], rr2[i + 1], a1);
            }
            a0 = fma2(wrr2[24], rr2[24], a0);
            float tail = 0.0f;
            if (s < 20) {                                // I_kc partial sums
                const u64* p2 = (const u64*)(sPart + s * 56 + h * 28);
#pragma unroll
                for (int i = 0; i < 12; i += 2) {
                    a0 = add2(a0, p2[i]);
                    a1 = add2(a1, p2[i + 1]);
                }
                tail = (sPart + s * 56 + h * 28)[24];
            }
            float f0, f1, f2, f3;
            upk(a0, f0, f1); upk(a1, f2, f3);
            float acc = (f0 + f1) + (f2 + f3) + tail;
            if (h == 0) {
                float I = (s >= 20 && s < 80) ? sIfbn[t * 60 + (s - 20)] : 0.0f;
                acc += sbias[s] + I;
            }
            unsigned msk = (tid < 192) ? 0xFFFFFFFFu : 0x000000FFu;
            acc += __shfl_xor_sync(msk, acc, 1);
            if (h == 0) {
                float act  = fmaxf(acc, 0.0f);
                float rold = sr[s];
                float rn   = rold + (act - rold) * dt;   // TAU_R = 1
                srn[s] = rn;
                __stcs(out + ((size_t)(t + 1) * nb + b) * 100 + s, rn);
                if (s >= 80) {                           // DAN trace, ONE STS.128
                    int d = s - 80;
                    float nv = srbd[d] + (rn - srbd[d]) * dtw;
                    srbd[d] = nv;
                    *(float4*)(sDN + 4 * d) = make_float4(nv, nv, -rn, -rn);
                }
            }
        } else {
            int u = tid - 200;                           // rbk: 100 u64s, packed
            u64* rb2 = (u64*)srbk;
            const u64* rk2 = (const u64*)srkC;
            {
                u64 rb = rb2[u];
                u64 d = fma2(rb, NEG12, rk2[u]);
                rb2[u] = fma2(d, DTW2, rb);
            }
            if (u < 44) {
                int k = u + 56;
                u64 rb = rb2[k];
                u64 d = fma2(rb, NEG12, rk2[k]);
                rb2[k] = fma2(d, DTW2, rb);
            }
        }
        __syncthreads();

        // ---- Phase D: plasticity + streamed stores + next sPart ----
        if (wid == 0) {                                  // readout[t+1]
            float p = (lane < 20) ? sWro[lane] * srn[lane] : 0.0f;
            p += __shfl_xor_sync(0xffffffffu, p, 16);
            p += __shfl_xor_sync(0xffffffffu, p, 8);
            p += __shfl_xor_sync(0xffffffffu, p, 4);
            p += __shfl_xor_sync(0xffffffffu, p, 2);
            p += __shfl_xor_sync(0xffffffffu, p, 1);
            if (lane == 0) out[OFF_RO + (size_t)(t + 1) * nb + b] = p;
        }
        {
            float4* oW4  = (float4*)(out + OFF_W  + ((size_t)(t + 1) * nb + b) * 4000) + tid;
            float4* owt4 = (float4*)(out + OFF_WT + ((size_t)(t + 1) * nb + b) * 4000) + tid;
            const ulonglong2* rkv  = (const ulonglong2*)srkC;
            const ulonglong2* rnv  = (const ulonglong2*)(srkC + 200);
            const ulonglong2* rbkv = (const ulonglong2*)srbk;
#pragma unroll
            for (int j = 0; j < 4; j++) {
                if (val_[j]) {
                    int m  = m_[j];
                    int kq = kq_[j];
                    ulonglong2 dn = *(const ulonglong2*)(sDN + 4 * m); // LDS.128
                    u64 rbd2 = dn.x;                     // {rbd, rbd}
                    u64 nrd2 = dn.y;                     // {-rdan, -rdan}
                    ulonglong2 rk = rkv[kq];
                    ulonglong2 rb = rbkv[kq];
                    u64 t0 = mul2(rbd2, rk.x);
                    t0 = fma2(nrd2, rb.x, t0);
                    rwt2[2 * j] = fma2(t0, DT2, rwt2[2 * j]);
                    u64 t1 = mul2(rbd2, rk.y);
                    t1 = fma2(nrd2, rb.y, t1);
                    rwt2[2 * j + 1] = fma2(t1, DT2, rwt2[2 * j + 1]);
                    float wtx, wty, wtz, wtw;
                    upk(rwt2[2 * j], wtx, wty);
                    upk(rwt2[2 * j + 1], wtz, wtw);
                    float4 w = rw[j];
                    w.x = fminf(fmaxf(fmaf(wtx - w.x, dtw, w.x), 0.0f), 0.05f);
                    w.y = fminf(fmaxf(fmaf(wty - w.y, dtw, w.y), 0.0f), 0.05f);
                    w.z = fminf(fmaxf(fmaf(wtz - w.z, dtw, w.z), 0.0f), 0.05f);
                    w.w = fminf(fmaxf(fmaf(wtw - w.w, dtw, w.w), 0.0f), 0.05f);
                    rw[j] = w;
                    // partial I_kc(t+1) with freshly-updated W
                    ulonglong2 xn = rnv[kq];
                    u64 a = mul2(pk(w.x, w.y), xn.x);
                    a = fma2(pk(w.z, w.w), xn.y, a);
                    float alo, ahi; upk(a, alo, ahi);
                    sPart[sp_[j]] = alo + ahi;
                    __stcs(oW4  + 256 * j, w);           // W_series[t+1]
                    __stcs(owt4 + 256 * j, make_float4(wtx, wty, wtz, wtw));
                }
            }
        }
        if (tid < 100) sr[tid] = srn[tid];               // carry r
        srkC += 200;
        __syncthreads();
    }
}

extern "C" void kernel_launch(void* const* d_in, const int* in_sizes, int n_in,
                              void* d_out, int out_size)
{
    const float* r_kc   = (const float*)d_in[0];
    const float* r_ext  = (const float*)d_in[1];
    // d_in[2] = time (dt = 0.5 exact), d_in[3] = n_batch scalar
    const float* W0_W   = (const float*)d_in[4];
    const float* W0_w   = (const float*)d_in[5];
    const float* W_rec  = (const float*)d_in[6];
    const float* W_ext  = (const float*)d_in[7];
    const float* bias   = (const float*)d_in[8];
    const float* W_ro   = (const float*)d_in[9];

    int nb = in_sizes[0] / (200 * 61);   // 256

    size_t smem = SMEM_FLOATS * sizeof(float);   // 70160 B
    cudaFuncSetAttribute(rnn_kernel, cudaFuncAttributeMaxDynamicSharedMemorySize,
                         (int)smem);

    rnn_kernel<<<nb, TPB, smem>>>(r_kc, r_ext, W0_W, W0_w, W_rec,
                                  W_ext, bias, W_ro, (float*)d_out, nb);
}

// round 16
// speedup vs baseline: 1.0887x; 1.0335x over previous
#include <cuda_runtime.h>

#define TPB 256
typedef unsigned long long u64;

// smem floats:
// srkT 12200 | sIfbn 3600 | sPart 20*56=1120 | srbk 200 | srr 2*100 | srn 100 |
// sbias 100 | sWro 20 | srbd 20 | sDN 80  => 17640 floats = 70560 B
#define SMEM_FLOATS 17640

__device__ __forceinline__ u64 pk(float lo, float hi) {
    u64 r; asm("mov.b64 %0,{%1,%2};" : "=l"(r) : "f"(lo), "f"(hi)); return r;
}
__device__ __forceinline__ void upk(u64 v, float& lo, float& hi) {
    asm("mov.b64 {%0,%1},%2;" : "=f"(lo), "=f"(hi) : "l"(v));
}
__device__ __forceinline__ u64 fma2(u64 a, u64 b, u64 c) {
    u64 d; asm("fma.rn.f32x2 %0,%1,%2,%3;" : "=l"(d) : "l"(a), "l"(b), "l"(c)); return d;
}
__device__ __forceinline__ u64 mul2(u64 a, u64 b) {
    u64 d; asm("mul.rn.f32x2 %0,%1,%2;" : "=l"(d) : "l"(a), "l"(b)); return d;
}
__device__ __forceinline__ u64 add2(u64 a, u64 b) {
    u64 d; asm("add.rn.f32x2 %0,%1,%2;" : "=l"(d) : "l"(a), "l"(b)); return d;
}

__global__ void __launch_bounds__(256, 2)
rnn_kernel(const float* __restrict__ r_kc, const float* __restrict__ r_ext,
           const float* __restrict__ W0_W, const float* __restrict__ W0_w,
           const float* __restrict__ W_recur, const float* __restrict__ W_ext,
           const float* __restrict__ bias, const float* __restrict__ W_readout,
           float* __restrict__ out, int nb)
{
    const int b   = blockIdx.x;
    const int tid = threadIdx.x;
    const int wid = tid >> 5, lane = tid & 31;

    extern __shared__ float smem[];
    float* srkT   = smem;            // 12200 : rk [t*200+k], 61 steps
    float* sIfbn  = smem + 12200;    // 3600  : precomputed I_fbn [t*60+f]
    float* sPart  = smem + 15800;    // 1120  : partials, row stride 56, gap 25..27
    float* srbk   = smem + 16920;    // 200
    float* srr    = smem + 17120;    // 2*100 : r double buffer
    float* srn    = smem + 17320;    // 100
    float* sbias  = smem + 17420;    // 100
    float* sWro   = smem + 17520;    // 20
    float* srbd   = smem + 17540;    // 20
    float* sDN    = smem + 17560;    // 80 : float4[m] = {rbd,rbd,-rdan,-rdan}

    const float dt  = 0.5f;   // time = arange*0.5 -> exact
    const float dtw = 0.1f;   // dt / TAU_W
    const u64 DT2   = pk(dt, dt);
    const u64 DTW2  = pk(dtw, dtw);
    const u64 NEG12 = pk(-1.0f, -1.0f);

    const size_t nb4000 = (size_t)nb * 4000;
    const size_t OFF_W  = (size_t)61 * nb * 100;
    const size_t OFF_WT = OFF_W + (size_t)61 * nb4000;
    const size_t OFF_RO = OFF_WT + (size_t)61 * nb4000;

    // ---- init: bulk-load rk (transposed), precompute I_fbn for all steps ----
    const float* rkb = r_kc  + (size_t)b * (200 * 61);
    const float* reb = r_ext + (size_t)b * (2 * 61);
    for (int idx = tid; idx < 12200; idx += TPB) {
        int k = idx / 61, t = idx - k * 61;
        srkT[t * 200 + k] = rkb[idx];
    }
    for (int idx = tid; idx < 3600; idx += TPB) {
        int t = idx / 60, f = idx - t * 60;
        sIfbn[idx] = W_ext[2 * f] * reb[t] + W_ext[2 * f + 1] * reb[61 + t];
    }
    if (tid < 100) sbias[tid] = bias[tid];
    if (tid < 20)  { sWro[tid] = W_readout[tid]; srbd[tid] = 0.1f; }
    if (tid < 100) {
        float v = (tid < 20) ? 0.0f : 0.1f;
        srr[tid] = v;                                   // buffer 0 = r(0)
        out[(size_t)b * 100 + tid] = v;                 // r_series[0]
    }
    if (tid == 0) out[OFF_RO + b] = 0.0f;               // readout[0]

    // ---- Wr in packed registers: thread t<200 -> row s=t>>1, half h=t&1 ----
    const int s = tid >> 1, h = tid & 1;
    u64 wrr2[25];
    if (tid < 200) {
        const float2* src = (const float2*)(W_recur + s * 100 + h * 50);
#pragma unroll
        for (int i = 0; i < 25; i++) {
            float2 v = src[i];
            if (s < 20) {                                // MBON<-DAN zeroed
                int jcol = h * 50 + 2 * i;
                if (jcol >= 80) v.x = 0.0f;
                if (jcol + 1 >= 80) v.y = 0.0f;
            }
            wrr2[i] = pk(v.x, v.y);
        }
    } else {
#pragma unroll
        for (int i = 0; i < 25; i++) wrr2[i] = 0ull;
    }

    // ---- per-thread loop-invariant chunk geometry ----
    int m_[4], kq_[4], sp_[4];
    bool val_[4];
#pragma unroll
    for (int j = 0; j < 4; j++) {
        int c = tid + TPB * j; if (c > 999) c = 999;
        val_[j] = (tid + TPB * j) < 1000;
        int m = c / 50, kq = c - m * 50;
        m_[j] = m; kq_[j] = kq;
        sp_[j] = m * 56 + kq + ((kq >= 25) ? 3 : 0);
    }

    // ---- W (float4) + wt (packed u64) state + series[0] stores ----
    float4 rw[4];
    u64 rwt2[8];
    {
        const float4* gW0 = (const float4*)(W0_W + (size_t)b * 4000);
        const ulonglong2* gw0 = (const ulonglong2*)(W0_w + (size_t)b * 4000);
        float4* oW0  = (float4*)(out + OFF_W  + (size_t)b * 4000) + tid;
        float4* owt0 = (float4*)(out + OFF_WT + (size_t)b * 4000) + tid;
#pragma unroll
        for (int j = 0; j < 4; j++) {
            if (val_[j]) {
                int c = tid + TPB * j;
                float4 w = gW0[c];
                ulonglong2 wt = gw0[c];
                rw[j] = w; rwt2[2 * j] = wt.x; rwt2[2 * j + 1] = wt.y;
                __stcs(oW0 + 256 * j, w);
                float a, b2, c2, d2; upk(wt.x, a, b2); upk(wt.y, c2, d2);
                __stcs(owt0 + 256 * j, make_float4(a, b2, c2, d2));
            }
        }
    }
    __syncthreads();

    // ---- rbk0 + seed sPart = W0 . rk(0) ----
    if (tid < 200) srbk[tid] = srkT[tid];
    {
        const float4* rk4 = (const float4*)srkT;        // t = 0
#pragma unroll
        for (int j = 0; j < 4; j++) {
            if (val_[j]) {
                float4 x = rk4[kq_[j]];
                float4 w = rw[j];
                sPart[sp_[j]] = w.x * x.x + w.y * x.y + w.z * x.z + w.w * x.w;
            }
        }
    }
    __syncthreads();

    const float* srkC = srkT;                           // rk(t) running ptr

    // ---- 60 steps, 2 barriers each ----
    for (int t = 0; t < 60; t++) {
        const float* scur = srr + 100 * (t & 1);        // r(t)
        float*       snxt = srr + 100 * (1 - (t & 1));  // r(t+1)

        // ---- Phase B: r dynamics (packed register matvec) / rbk update ----
        if (tid < 200) {
            const u64* rr2 = (const u64*)(scur + h * 50);
            u64 a0 = 0ull, a1 = 0ull;
#pragma unroll
            for (int i = 0; i < 24; i += 2) {
                a0 = fma2(wrr2[i],     rr2[i],     a0);
                a1 = fma2(wrr2[i + 1], rr2[i + 1], a1);
            }
            a0 = fma2(wrr2[24], rr2[24], a0);
            float tail = 0.0f;
            if (s < 20) {                                // I_kc partial sums
                const u64* p2 = (const u64*)(sPart + s * 56 + h * 28);
#pragma unroll
                for (int i = 0; i < 12; i += 2) {
                    a0 = add2(a0, p2[i]);
                    a1 = add2(a1, p2[i + 1]);
                }
                tail = (sPart + s * 56 + h * 28)[24];
            }
            float f0, f1, f2, f3;
            upk(a0, f0, f1); upk(a1, f2, f3);
            float acc = (f0 + f1) + (f2 + f3) + tail;
            if (h == 0) {
                float I = (s >= 20 && s < 80) ? sIfbn[t * 60 + (s - 20)] : 0.0f;
                acc += sbias[s] + I;
            }
            unsigned msk = (tid < 192) ? 0xFFFFFFFFu : 0x000000FFu;
            acc += __shfl_xor_sync(msk, acc, 1);
            if (h == 0) {
                float act  = fmaxf(acc, 0.0f);
                float rold = scur[s];
                float rn   = rold + (act - rold) * dt;   // TAU_R = 1
                srn[s]  = rn;
                snxt[s] = rn;                            // r(t+1) for next matvec
                __stcs(out + ((size_t)(t + 1) * nb + b) * 100 + s, rn);
                if (s >= 80) {                           // DAN trace, ONE STS.128
                    int d = s - 80;
                    float nv = srbd[d] + (rn - srbd[d]) * dtw;
                    srbd[d] = nv;
                    *(float4*)(sDN + 4 * d) = make_float4(nv, nv, -rn, -rn);
                }
            }
        } else {
            int u = tid - 200;                           // rbk: 100 u64s, packed
            u64* rb2 = (u64*)srbk;
            const u64* rk2 = (const u64*)srkC;
            {
                u64 rb = rb2[u];
                u64 d = fma2(rb, NEG12, rk2[u]);
                rb2[u] = fma2(d, DTW2, rb);
            }
            if (u < 44) {
                int k = u + 56;
                u64 rb = rb2[k];
                u64 d = fma2(rb, NEG12, rk2[k]);
                rb2[k] = fma2(d, DTW2, rb);
            }
        }
        __syncthreads();

        // ---- Phase D: plasticity + streamed stores + next sPart ----
        if (wid == 0) {                                  // readout[t+1]
            float p = (lane < 20) ? sWro[lane] * srn[lane] : 0.0f;
            p += __shfl_xor_sync(0xffffffffu, p, 16);
            p += __shfl_xor_sync(0xffffffffu, p, 8);
            p += __shfl_xor_sync(0xffffffffu, p, 4);
            p += __shfl_xor_sync(0xffffffffu, p, 2);
            p += __shfl_xor_sync(0xffffffffu, p, 1);
            if (lane == 0) out[OFF_RO + (size_t)(t + 1) * nb + b] = p;
        }
        {
            float4* oW4  = (float4*)(out + OFF_W  + ((size_t)(t + 1) * nb + b) * 4000) + tid;
            float4* owt4 = (float4*)(out + OFF_WT + ((size_t)(t + 1) * nb + b) * 4000) + tid;
            const ulonglong2* rkv  = (const ulonglong2*)srkC;
            const ulonglong2* rnv  = (const ulonglong2*)(srkC + 200);
            const ulonglong2* rbkv = (const ulonglong2*)srbk;
#pragma unroll
            for (int j = 0; j < 4; j++) {
                if (val_[j]) {
                    int m  = m_[j];
                    int kq = kq_[j];
                    ulonglong2 dn = *(const ulonglong2*)(sDN + 4 * m); // LDS.128
                    u64 rbd2 = dn.x;                     // {rbd, rbd}
                    u64 nrd2 = dn.y;                     // {-rdan, -rdan}
                    ulonglong2 rk = rkv[kq];
                    ulonglong2 rb = rbkv[kq];
                    u64 t0 = mul2(rbd2, rk.x);
                    t0 = fma2(nrd2, rb.x, t0);
                    rwt2[2 * j] = fma2(t0, DT2, rwt2[2 * j]);
                    u64 t1 = mul2(rbd2, rk.y);
                    t1 = fma2(nrd2, rb.y, t1);
                    rwt2[2 * j + 1] = fma2(t1, DT2, rwt2[2 * j + 1]);
                    float wtx, wty, wtz, wtw;
                    upk(rwt2[2 * j], wtx, wty);
                    upk(rwt2[2 * j + 1], wtz, wtw);
                    float4 w = rw[j];
                    w.x = fminf(fmaxf(fmaf(wtx - w.x, dtw, w.x), 0.0f), 0.05f);
                    w.y = fminf(fmaxf(fmaf(wty - w.y, dtw, w.y), 0.0f), 0.05f);
                    w.z = fminf(fmaxf(fmaf(wtz - w.z, dtw, w.z), 0.0f), 0.05f);
                    w.w = fminf(fmaxf(fmaf(wtw - w.w, dtw, w.w), 0.0f), 0.05f);
                    rw[j] = w;
                    // partial I_kc(t+1) with freshly-updated W
                    ulonglong2 xn = rnv[kq];
                    u64 a = mul2(pk(w.x, w.y), xn.x);
                    a = fma2(pk(w.z, w.w), xn.y, a);
                    float alo, ahi; upk(a, alo, ahi);
                    sPart[sp_[j]] = alo + ahi;
                    __stcs(oW4  + 256 * j, w);           // W_series[t+1]
                    __stcs(owt4 + 256 * j, make_float4(wtx, wty, wtz, wtw));
                }
            }
        }
        srkC += 200;
        __syncthreads();
    }
}

extern "C" void kernel_launch(void* const* d_in, const int* in_sizes, int n_in,
                              void* d_out, int out_size)
{
    const float* r_kc   = (const float*)d_in[0];
    const float* r_ext  = (const float*)d_in[1];
    // d_in[2] = time (dt = 0.5 exact), d_in[3] = n_batch scalar
    const float* W0_W   = (const float*)d_in[4];
    const float* W0_w   = (const float*)d_in[5];
    const float* W_rec  = (const float*)d_in[6];
    const float* W_ext  = (const float*)d_in[7];
    const float* bias   = (const float*)d_in[8];
    const float* W_ro   = (const float*)d_in[9];

    int nb = in_sizes[0] / (200 * 61);   // 256

    size_t smem = SMEM_FLOATS * sizeof(float);   // 70560 B
    cudaFuncSetAttribute(rnn_kernel, cudaFuncAttributeMaxDynamicSharedMemorySize,
                         (int)smem);

    rnn_kernel<<<nb, TPB, smem>>>(r_kc, r_ext, W0_W, W0_w, W_rec,
                                  W_ext, bias, W_ro, (float*)d_out, nb);
}